// round 16
// baseline (speedup 1.0000x reference)
#include <cuda_runtime.h>
#include <cuda_fp16.h>
#include <math.h>
#include <stdint.h>

// INGP hashgrid encoding.
//   out[n, l*2+f] = sum_{8 corners} w_c * tables[l, hash(corner)&(T-1), f]
// N=524288, L=16, T=2^19, F=2.
//
// Cost model (validated over 7 rounds): time ~ per-lane scattered load-
// instruction count through l1tex (~1cyc each), hit/miss-independent.
// So: minimize loads per (point,level).
//  - Levels 0-5 (res 16..80): pre-gathered DENSE QUADS. For each cell x-plane
//    we store the 4 (y,z)-corner feature pairs as fp16 (scaled by 2^13 to
//    avoid subnormals; exact power-2 scaling) packed in 16B -> ONE LDG.128.
//    A point needs 2 quads (x and x+1) -> 2 loads/level instead of 6.
//  - Levels 6-15: hashed, even-ix float4 pairing (hash uses prime 1 on x:
//    even ix -> x-corners at h and h^1 share one aligned float4), .cg.

#define NPTS   524288
#define NLEV   16
#define TSIZE  (1u << 19)
#define HMASK  (TSIZE - 1u)
#define PRIME1 2654435761u
#define PRIME2 805459861u

#define NDLEV  6          // dense levels 0..5, res = 16,22,30,42,58,80
// quad grid for level res R: dims (R+1) x R x R  (x-plane, y, z)
// counts: 17*256=4352, 23*484=11132, 31*900=27900, 43*1764=75852,
//         59*3364=198476, 81*6400=518400 ; total 836112
#define NQUADS 836112
#define QSCALE 8192.0f     // 2^13
#define QINV   (1.0f/8192.0f)

struct ResArr  { float r[NLEV]; };
struct QuadCfg { int base[NDLEV + 1]; int R[NDLEV]; };

__device__ uint4 g_quads[NQUADS];   // 13.4 MB

// ---- prefix: build fp16 quads for levels 0..5 ----
__global__ void ingp_quad_build(const float2* __restrict__ tables, QuadCfg cfg)
{
    int id = blockIdx.x * blockDim.x + threadIdx.x;
    if (id >= NQUADS) return;

    int l = NDLEV - 1;
    #pragma unroll
    for (int k = 0; k < NDLEV - 1; k++)
        if (id < cfg.base[k + 1]) { l = k; break; }

    int j  = id - cfg.base[l];
    int R  = cfg.R[l];
    int qz = j % R;
    int t2 = j / R;
    int qy = t2 % R;
    int qx = t2 / R;

    const float2* __restrict__ tab = tables + (size_t)l * TSIZE;

    uint32_t hx  = (uint32_t)qx;
    uint32_t hy0 = (uint32_t)qy * PRIME1;
    uint32_t hy1 = hy0 + PRIME1;
    uint32_t hz0 = (uint32_t)qz * PRIME2;
    uint32_t hz1 = hz0 + PRIME2;

    float2 a = tab[(hx ^ hy0 ^ hz0) & HMASK];   // (y0,z0)
    float2 b = tab[(hx ^ hy0 ^ hz1) & HMASK];   // (y0,z1)
    float2 c = tab[(hx ^ hy1 ^ hz0) & HMASK];   // (y1,z0)
    float2 d = tab[(hx ^ hy1 ^ hz1) & HMASK];   // (y1,z1)

    uint4 q;
    __half2 ha = __floats2half2_rn(a.x * QSCALE, a.y * QSCALE);
    __half2 hb = __floats2half2_rn(b.x * QSCALE, b.y * QSCALE);
    __half2 hc = __floats2half2_rn(c.x * QSCALE, c.y * QSCALE);
    __half2 hd = __floats2half2_rn(d.x * QSCALE, d.y * QSCALE);
    q.x = *reinterpret_cast<unsigned*>(&ha);
    q.y = *reinterpret_cast<unsigned*>(&hb);
    q.z = *reinterpret_cast<unsigned*>(&hc);
    q.w = *reinterpret_cast<unsigned*>(&hd);
    g_quads[id] = q;
}

// ---- main kernel: 16 threads per point, lane = level ----
__global__ __launch_bounds__(256) void ingp_encode_kernel(
    const float*  __restrict__ pts,     // [N,3]
    const float2* __restrict__ tables,  // [L,T] float2
    float2*       __restrict__ out,     // [N,16] float2
    ResArr res, QuadCfg cfg)
{
    int t = blockIdx.x * blockDim.x + threadIdx.x;   // exact grid: N*16/256
    int n = t >> 4;          // point
    int l = t & 15;          // level

    // 16 consecutive threads share a point -> L1 broadcast
    float px = pts[3 * n + 0];
    float py = pts[3 * n + 1];
    float pz = pts[3 * n + 2];

    // x = (p + 1)/2 — exact ops, no FMA contraction
    float xs = __fmul_rn(__fadd_rn(px, 1.0f), 0.5f);
    float ys = __fmul_rn(__fadd_rn(py, 1.0f), 0.5f);
    float zs = __fmul_rn(__fadd_rn(pz, 1.0f), 0.5f);

    float r = res.r[l];
    float posx = __fmul_rn(xs, r);
    float posy = __fmul_rn(ys, r);
    float posz = __fmul_rn(zs, r);

    float fx = floorf(posx), fy = floorf(posy), fz = floorf(posz);
    float wx = __fsub_rn(posx, fx);
    float wy = __fsub_rn(posy, fy);
    float wz = __fsub_rn(posz, fz);

    uint32_t ix = (uint32_t)fx;
    uint32_t iy = (uint32_t)fy;
    uint32_t iz = (uint32_t)fz;

    // Corner values in CORNERS order: v0 = x-corner 0, v1 = x-corner 1,
    // each over (y,z) pairs [y0z0, y0z1, y1z0, y1z1]
    float2 v0[4], v1[4];
    float fin = 1.0f;

    if (l < NDLEV) {
        // ---- dense fp16-quad path: 2 x LDG.128 ----
        int R  = cfg.R[l];
        int q0 = cfg.base[l] + (int)ix * (R * R) + (int)iy * R + (int)iz;
        uint4 qa = g_quads[q0];            // x-plane ix
        uint4 qb = g_quads[q0 + R * R];    // x-plane ix+1
        v0[0] = __half22float2(*reinterpret_cast<__half2*>(&qa.x));
        v0[1] = __half22float2(*reinterpret_cast<__half2*>(&qa.y));
        v0[2] = __half22float2(*reinterpret_cast<__half2*>(&qa.z));
        v0[3] = __half22float2(*reinterpret_cast<__half2*>(&qa.w));
        v1[0] = __half22float2(*reinterpret_cast<__half2*>(&qb.x));
        v1[1] = __half22float2(*reinterpret_cast<__half2*>(&qb.y));
        v1[2] = __half22float2(*reinterpret_cast<__half2*>(&qb.z));
        v1[3] = __half22float2(*reinterpret_cast<__half2*>(&qb.w));
        fin = QINV;                        // exact power-2 unscale
    } else {
        // ---- hashed path (levels 6-15) ----
        uint32_t hy0 = iy * PRIME1;
        uint32_t hy1 = hy0 + PRIME1;
        uint32_t hz0 = iz * PRIME2;
        uint32_t hz1 = hz0 + PRIME2;
        uint32_t rest[4];
        rest[0] = hy0 ^ hz0;
        rest[1] = hy0 ^ hz1;
        rest[2] = hy1 ^ hz0;
        rest[3] = hy1 ^ hz1;

        const float2* __restrict__ tab = tables + (size_t)l * TSIZE;

        if ((ix & 1u) == 0u) {
            // even ix: x-corners h and h^1 share one aligned float4
            const float4* tab4 = (const float4*)tab;
            #pragma unroll
            for (int i = 0; i < 4; i++) {
                uint32_t b = (ix ^ rest[i]) & HMASK;
                float4 q = __ldcg(tab4 + (b >> 1));
                bool lo = (b & 1u) == 0u;
                v0[i] = lo ? make_float2(q.x, q.y) : make_float2(q.z, q.w);
                v1[i] = lo ? make_float2(q.z, q.w) : make_float2(q.x, q.y);
            }
        } else {
            uint32_t ix1 = ix + 1u;
            #pragma unroll
            for (int i = 0; i < 4; i++) {
                v0[i] = __ldcg(tab + ((ix  ^ rest[i]) & HMASK));
                v1[i] = __ldcg(tab + ((ix1 ^ rest[i]) & HMASK));
            }
        }
    }

    // Trilinear weights (corner bit set -> w, else 1-w), CORNERS order
    float ux0 = 1.0f - wx, ux1 = wx;
    float uy0 = 1.0f - wy, uy1 = wy;
    float uz0 = 1.0f - wz, uz1 = wz;

    float w000 = ux0 * uy0 * uz0;
    float w001 = ux0 * uy0 * uz1;
    float w010 = ux0 * uy1 * uz0;
    float w011 = ux0 * uy1 * uz1;
    float w100 = ux1 * uy0 * uz0;
    float w101 = ux1 * uy0 * uz1;
    float w110 = ux1 * uy1 * uz0;
    float w111 = ux1 * uy1 * uz1;

    float2 acc;
    acc.x = w000 * v0[0].x + w001 * v0[1].x + w010 * v0[2].x + w011 * v0[3].x
          + w100 * v1[0].x + w101 * v1[1].x + w110 * v1[2].x + w111 * v1[3].x;
    acc.y = w000 * v0[0].y + w001 * v0[1].y + w010 * v0[2].y + w011 * v0[3].y
          + w100 * v1[0].y + w101 * v1[1].y + w110 * v1[2].y + w111 * v1[3].y;

    acc.x *= fin;
    acc.y *= fin;

    out[(size_t)n * NLEV + l] = acc;   // 16 consecutive float2 per point group
}

// ---------------- host ----------------

extern "C" void kernel_launch(void* const* d_in, const int* in_sizes, int n_in,
                              void* d_out, int out_size)
{
    const float*  pts    = (const float*)d_in[0];   // [N,3]
    const float2* tables = (const float2*)d_in[1];  // [L,T,2] -> [L,T] float2

    // Replicate numpy RES exactly (float64 libm chain)
    ResArr res;
    double growth = exp((log(2048.0) - log(16.0)) / 15.0);
    for (int l = 0; l < NLEV; l++)
        res.r[l] = (float)floor(16.0 * pow(growth, (double)l));

    // Quad layout from the SAME res values (R = 16,22,30,42,58,80)
    QuadCfg cfg;
    {
        int off = 0;
        for (int l = 0; l < NDLEV; l++) {
            int R = (int)res.r[l];
            cfg.R[l]    = R;
            cfg.base[l] = off;
            off += (R + 1) * R * R;
        }
        cfg.base[NDLEV] = off;   // == NQUADS (836112)
    }

    ingp_quad_build<<<(NQUADS + 255) / 256, 256>>>(tables, cfg);

    int total = NPTS * NLEV;                        // 8388608
    ingp_encode_kernel<<<total / 256, 256>>>(pts, tables, (float2*)d_out, res, cfg);
}